// round 1
// baseline (speedup 1.0000x reference)
#include <cuda_runtime.h>
#include <math.h>

#define B_ 4
#define S_ 2048
#define DM 512
#define H_ 8
#define DK 64

// Scratch (device globals — no runtime allocation allowed)
__device__ float g_buf[(size_t)B_*S_*DM];  // LN output, reused 4x
__device__ float g_qp [(size_t)B_*S_*DM];  // Q projection [B,S,512]
__device__ float g_kp [(size_t)B_*S_*DM];  // K projection
__device__ float g_vp [(size_t)B_*S_*DM];  // V projection
__device__ float g_oh [(size_t)B_*S_*DM];  // attention output (merged heads)

// ---------------- LayerNorm: one block per row of 512 ----------------
__global__ void ln_kernel(const float* __restrict__ x, float* __restrict__ y,
                          const float* __restrict__ g, const float* __restrict__ bb) {
    int row = blockIdx.x;
    int tid = threadIdx.x;                   // 256 threads
    const float* xr = x + (size_t)row * DM;
    float v0 = xr[tid], v1 = xr[tid + 256];
    __shared__ float red[256];
    red[tid] = v0 + v1;
    __syncthreads();
    for (int o = 128; o > 0; o >>= 1) { if (tid < o) red[tid] += red[tid + o]; __syncthreads(); }
    float mu = red[0] * (1.0f / DM);
    __syncthreads();
    float d0 = v0 - mu, d1 = v1 - mu;
    red[tid] = d0 * d0 + d1 * d1;
    __syncthreads();
    for (int o = 128; o > 0; o >>= 1) { if (tid < o) red[tid] += red[tid + o]; __syncthreads(); }
    float rstd = rsqrtf(red[0] * (1.0f / DM) + 1e-5f);
    float* yr = y + (size_t)row * DM;
    yr[tid]       = d0 * rstd * g[tid]       + bb[tid];
    yr[tid + 256] = d1 * rstd * g[tid + 256] + bb[tid + 256];
}

// ---------------- Projection GEMM: C[M,512] = A[M,512] @ W^T ----------------
// grid (512/64, M/64), 256 threads, 64x64 tile, 4x4 per thread
__global__ void proj_gemm(const float* __restrict__ A, const float* __restrict__ W,
                          float* __restrict__ C) {
    __shared__ float As[64][33];
    __shared__ float Ws[64][33];
    int tid = threadIdx.x;
    int tx = tid & 15, ty = tid >> 4;
    int m0 = blockIdx.y * 64;
    int n0 = blockIdx.x * 64;
    float acc[4][4] = {};
    for (int k0 = 0; k0 < DM; k0 += 32) {
        for (int e = tid; e < 64 * 32; e += 256) {
            int m = e >> 5, kk = e & 31;
            As[m][kk] = A[(size_t)(m0 + m) * DM + k0 + kk];
            Ws[m][kk] = W[(size_t)(n0 + m) * DM + k0 + kk];
        }
        __syncthreads();
        #pragma unroll
        for (int kk = 0; kk < 32; kk++) {
            float a[4], bv[4];
            #pragma unroll
            for (int r = 0; r < 4; r++) a[r] = As[ty * 4 + r][kk];
            #pragma unroll
            for (int c = 0; c < 4; c++) bv[c] = Ws[tx * 4 + c][kk];
            #pragma unroll
            for (int r = 0; r < 4; r++)
                #pragma unroll
                for (int c = 0; c < 4; c++) acc[r][c] += a[r] * bv[c];
        }
        __syncthreads();
    }
    #pragma unroll
    for (int r = 0; r < 4; r++)
        #pragma unroll
        for (int c = 0; c < 4; c++)
            C[(size_t)(m0 + ty * 4 + r) * DM + n0 + tx * 4 + c] = acc[r][c];
}

// ---------------- scores: attn_raw = scale * Q @ K^T per (b,h) ----------------
// grid (S/64 [sk], S/64 [sq], B*H), 256 threads
__global__ void scores_kernel(const float* __restrict__ qp, const float* __restrict__ kp,
                              float* __restrict__ attn) {
    __shared__ float Qs[64][65];
    __shared__ float Ks[64][65];
    int tid = threadIdx.x;
    int tx = tid & 15, ty = tid >> 4;
    int bh = blockIdx.z;
    int b = bh >> 3, h = bh & 7;
    int sq0 = blockIdx.y * 64, sk0 = blockIdx.x * 64;
    for (int e = tid; e < 64 * 64; e += 256) {
        int i = e >> 6, d = e & 63;
        Qs[i][d] = qp[((size_t)b * S_ + sq0 + i) * DM + h * 64 + d];
        Ks[i][d] = kp[((size_t)b * S_ + sk0 + i) * DM + h * 64 + d];
    }
    __syncthreads();
    float acc[4][4] = {};
    #pragma unroll
    for (int d = 0; d < 64; d++) {
        float a[4], bv[4];
        #pragma unroll
        for (int r = 0; r < 4; r++) a[r] = Qs[ty * 4 + r][d];
        #pragma unroll
        for (int c = 0; c < 4; c++) bv[c] = Ks[tx * 4 + c][d];
        #pragma unroll
        for (int r = 0; r < 4; r++)
            #pragma unroll
            for (int c = 0; c < 4; c++) acc[r][c] += a[r] * bv[c];
    }
    #pragma unroll
    for (int r = 0; r < 4; r++)
        #pragma unroll
        for (int c = 0; c < 4; c++)
            attn[((size_t)bh * S_ + sq0 + ty * 4 + r) * S_ + sk0 + tx * 4 + c]
                = 0.125f * acc[r][c];
}

// ---------------- softmax in place over rows of 2048 ----------------
__global__ void softmax_kernel(float* __restrict__ attn) {
    size_t row = blockIdx.x;
    float* p = attn + row * (size_t)S_;
    int tid = threadIdx.x;
    float v[8];
    float m = -1e30f;
    #pragma unroll
    for (int i = 0; i < 8; i++) { v[i] = p[i * 256 + tid]; m = fmaxf(m, v[i]); }
    __shared__ float red[256];
    red[tid] = m;
    __syncthreads();
    for (int o = 128; o > 0; o >>= 1) { if (tid < o) red[tid] = fmaxf(red[tid], red[tid + o]); __syncthreads(); }
    m = red[0];
    __syncthreads();
    float s = 0.f;
    #pragma unroll
    for (int i = 0; i < 8; i++) { v[i] = __expf(v[i] - m); s += v[i]; }
    red[tid] = s;
    __syncthreads();
    for (int o = 128; o > 0; o >>= 1) { if (tid < o) red[tid] += red[tid + o]; __syncthreads(); }
    float inv = 1.0f / red[0];
    #pragma unroll
    for (int i = 0; i < 8; i++) p[i * 256 + tid] = v[i] * inv;
}

// ---------------- oh = attn @ V per (b,h), merged-head output [B,S,512] ----------------
// grid (S/64 [sq], B*H), 256 threads
__global__ void av_kernel(const float* __restrict__ attn, const float* __restrict__ vp,
                          float* __restrict__ oh) {
    __shared__ float Ps[64][65];
    __shared__ float Vs[64][65];
    int tid = threadIdx.x;
    int tx = tid & 15, ty = tid >> 4;
    int bh = blockIdx.y;
    int b = bh >> 3, h = bh & 7;
    int sq0 = blockIdx.x * 64;
    float acc[4][4] = {};
    for (int sk0 = 0; sk0 < S_; sk0 += 64) {
        for (int e = tid; e < 64 * 64; e += 256) {
            int i = e >> 6, j = e & 63;
            Ps[i][j] = attn[((size_t)bh * S_ + sq0 + i) * S_ + sk0 + j];
            Vs[i][j] = vp[((size_t)b * S_ + sk0 + i) * DM + h * 64 + j];
        }
        __syncthreads();
        #pragma unroll
        for (int kk = 0; kk < 64; kk++) {
            float a[4], bv[4];
            #pragma unroll
            for (int r = 0; r < 4; r++) a[r] = Ps[ty * 4 + r][kk];
            #pragma unroll
            for (int c = 0; c < 4; c++) bv[c] = Vs[kk][tx * 4 + c];
            #pragma unroll
            for (int r = 0; r < 4; r++)
                #pragma unroll
                for (int c = 0; c < 4; c++) acc[r][c] += a[r] * bv[c];
        }
        __syncthreads();
    }
    #pragma unroll
    for (int r = 0; r < 4; r++)
        #pragma unroll
        for (int c = 0; c < 4; c++)
            oh[((size_t)b * S_ + sq0 + ty * 4 + r) * DM + h * 64 + tx * 4 + c] = acc[r][c];
}

extern "C" void kernel_launch(void* const* d_in, const int* in_sizes, int n_in,
                              void* d_out, int out_size) {
    const float* q    = (const float*)d_in[0];
    const float* k    = (const float*)d_in[1];
    const float* v    = (const float*)d_in[2];
    const float* W_Q  = (const float*)d_in[3];
    const float* W_K  = (const float*)d_in[4];
    const float* W_V  = (const float*)d_in[5];
    const float* W_fc = (const float*)d_in[6];
    const float* ln_g = (const float*)d_in[7];
    const float* ln_b = (const float*)d_in[8];

    float* out  = (float*)d_out;                       // [B,S,512]
    float* attn = out + (size_t)B_ * S_ * DM;          // [B,H,S,S]

    float *buf, *qp, *kp, *vp, *oh;
    cudaGetSymbolAddress((void**)&buf, g_buf);
    cudaGetSymbolAddress((void**)&qp,  g_qp);
    cudaGetSymbolAddress((void**)&kp,  g_kp);
    cudaGetSymbolAddress((void**)&vp,  g_vp);
    cudaGetSymbolAddress((void**)&oh,  g_oh);

    const int ROWS = B_ * S_;                          // 8192
    dim3 gemm_grid(DM / 64, ROWS / 64);                // (8, 128)

    // Q path
    ln_kernel<<<ROWS, 256>>>(q, buf, ln_g, ln_b);
    proj_gemm<<<gemm_grid, 256>>>(buf, W_Q, qp);
    // K path
    ln_kernel<<<ROWS, 256>>>(k, buf, ln_g, ln_b);
    proj_gemm<<<gemm_grid, 256>>>(buf, W_K, kp);
    // V path
    ln_kernel<<<ROWS, 256>>>(v, buf, ln_g, ln_b);
    proj_gemm<<<gemm_grid, 256>>>(buf, W_V, vp);

    // Attention
    scores_kernel<<<dim3(S_ / 64, S_ / 64, B_ * H_), 256>>>(qp, kp, attn);
    softmax_kernel<<<B_ * H_ * S_, 256>>>(attn);
    av_kernel<<<dim3(S_ / 64, B_ * H_), 256>>>(attn, vp, oh);

    // Output LN + fc
    ln_kernel<<<ROWS, 256>>>(oh, buf, ln_g, ln_b);
    proj_gemm<<<gemm_grid, 256>>>(buf, W_fc, out);
}

// round 6
// speedup vs baseline: 1.3424x; 1.3424x over previous
#include <cuda_runtime.h>
#include <math.h>

#define B_ 4
#define S_ 2048
#define DM 512
#define H_ 8

typedef unsigned long long ull;

__device__ __forceinline__ ull ffma2(ull a, ull b, ull c) {
    ull d;
    asm("fma.rn.f32x2 %0, %1, %2, %3;" : "=l"(d) : "l"(a), "l"(b), "l"(c));
    return d;
}
__device__ __forceinline__ ull pack2(float x, float y) {
    ull r;
    asm("mov.b64 %0, {%1, %2};" : "=l"(r) : "f"(x), "f"(y));
    return r;
}
__device__ __forceinline__ void unpack2(ull v, float& x, float& y) {
    asm("mov.b64 {%0, %1}, %2;" : "=f"(x), "=f"(y) : "l"(v));
}

// Scratch (device globals — no runtime allocation allowed)
__device__ float g_buf[(size_t)B_*S_*DM];
__device__ float g_qp [(size_t)B_*S_*DM];
__device__ float g_kp [(size_t)B_*S_*DM];
__device__ float g_vp [(size_t)B_*S_*DM];
__device__ float g_oh [(size_t)B_*S_*DM];

// ---------------- LayerNorm: one block per row of 512 ----------------
__global__ void ln_kernel(const float* __restrict__ x, float* __restrict__ y,
                          const float* __restrict__ g, const float* __restrict__ bb) {
    int row = blockIdx.x;
    int tid = threadIdx.x;                   // 256 threads
    const float* xr = x + (size_t)row * DM;
    float v0 = xr[tid], v1 = xr[tid + 256];
    __shared__ float red[256];
    red[tid] = v0 + v1;
    __syncthreads();
    for (int o = 128; o > 0; o >>= 1) { if (tid < o) red[tid] += red[tid + o]; __syncthreads(); }
    float mu = red[0] * (1.0f / DM);
    __syncthreads();
    float d0 = v0 - mu, d1 = v1 - mu;
    red[tid] = d0 * d0 + d1 * d1;
    __syncthreads();
    for (int o = 128; o > 0; o >>= 1) { if (tid < o) red[tid] += red[tid + o]; __syncthreads(); }
    float rstd = rsqrtf(red[0] * (1.0f / DM) + 1e-5f);
    float* yr = y + (size_t)row * DM;
    yr[tid]       = d0 * rstd * g[tid]       + bb[tid];
    yr[tid + 256] = d1 * rstd * g[tid + 256] + bb[tid + 256];
}

// =====================================================================
// GEMM micro-kernel (shared by proj / scores / av)
// Tile: 128 (rows) x 64 (cols), 256 threads, thread = 8 rows x 4 cols.
// smem transposed: As[k][m], Ws[k][n]. All smem reads are plain C++
// loads (LDS.128) so the compiler orders them against __syncthreads().
// Inner k-step: 2x ulonglong2 (a row pairs) + 1x float4 (b) + 4 pack
//               + 16 FFMA2.
// acc[pr][c] is f32x2 with lanes (row 2pr, row 2pr+1).
// =====================================================================

#define AT_PITCH 132   // 128 + 4 pad (floats); 528B row, 16B-aligned
#define BT_PITCH 68    // 64 + 4 pad; 272B row, 16B-aligned

__device__ __forceinline__ void mm_inner32(const float (*As)[AT_PITCH],
                                           const float (*Ws)[BT_PITCH],
                                           int ty, int tx, ull acc[4][4]) {
    #pragma unroll
    for (int kk = 0; kk < 32; kk++) {
        ulonglong2 a0 = *(const ulonglong2*)&As[kk][ty * 8];
        ulonglong2 a1 = *(const ulonglong2*)&As[kk][ty * 8 + 4];
        float4 bf = *(const float4*)&Ws[kk][tx * 4];
        ull b0 = pack2(bf.x, bf.x);
        ull b1 = pack2(bf.y, bf.y);
        ull b2 = pack2(bf.z, bf.z);
        ull b3 = pack2(bf.w, bf.w);
        ull ap0 = a0.x, ap1 = a0.y, ap2 = a1.x, ap3 = a1.y;
        acc[0][0] = ffma2(ap0, b0, acc[0][0]);
        acc[0][1] = ffma2(ap0, b1, acc[0][1]);
        acc[0][2] = ffma2(ap0, b2, acc[0][2]);
        acc[0][3] = ffma2(ap0, b3, acc[0][3]);
        acc[1][0] = ffma2(ap1, b0, acc[1][0]);
        acc[1][1] = ffma2(ap1, b1, acc[1][1]);
        acc[1][2] = ffma2(ap1, b2, acc[1][2]);
        acc[1][3] = ffma2(ap1, b3, acc[1][3]);
        acc[2][0] = ffma2(ap2, b0, acc[2][0]);
        acc[2][1] = ffma2(ap2, b1, acc[2][1]);
        acc[2][2] = ffma2(ap2, b2, acc[2][2]);
        acc[2][3] = ffma2(ap2, b3, acc[2][3]);
        acc[3][0] = ffma2(ap3, b0, acc[3][0]);
        acc[3][1] = ffma2(ap3, b1, acc[3][1]);
        acc[3][2] = ffma2(ap3, b2, acc[3][2]);
        acc[3][3] = ffma2(ap3, b3, acc[3][3]);
    }
}

// Load a 128x32 fp32 tile (row-major global, row stride ldg) transposed into As[k][m].
__device__ __forceinline__ void load_tileA_t(const float* __restrict__ src, size_t ldg,
                                             int tid, float (*As)[AT_PITCH]) {
    #pragma unroll
    for (int i = 0; i < 4; i++) {
        int lin = tid + i * 256;
        int m = lin >> 3, kg = (lin & 7) * 4;
        float4 f = *(const float4*)&src[(size_t)m * ldg + kg];
        As[kg    ][m] = f.x;
        As[kg + 1][m] = f.y;
        As[kg + 2][m] = f.z;
        As[kg + 3][m] = f.w;
    }
}

// Load a 64x32 fp32 tile transposed into Ws[k][n].
__device__ __forceinline__ void load_tileB_t(const float* __restrict__ src, size_t ldg,
                                             int tid, float (*Ws)[BT_PITCH]) {
    #pragma unroll
    for (int i = 0; i < 2; i++) {
        int lin = tid + i * 256;
        int n = lin >> 3, kg = (lin & 7) * 4;
        float4 f = *(const float4*)&src[(size_t)n * ldg + kg];
        Ws[kg    ][n] = f.x;
        Ws[kg + 1][n] = f.y;
        Ws[kg + 2][n] = f.z;
        Ws[kg + 3][n] = f.w;
    }
}

// ---------------- Projection GEMM: C[M,512] = A[M,512] @ W^T ----------------
__global__ __launch_bounds__(256) void proj_gemm(const float* __restrict__ A,
                                                 const float* __restrict__ W,
                                                 float* __restrict__ C) {
    __shared__ float As[32][AT_PITCH];
    __shared__ float Ws[32][BT_PITCH];
    int tid = threadIdx.x;
    int tx = tid & 15, ty = tid >> 4;
    int m0 = blockIdx.y * 128;
    int n0 = blockIdx.x * 64;
    ull acc[4][4] = {};
    for (int k0 = 0; k0 < DM; k0 += 32) {
        load_tileA_t(A + (size_t)m0 * DM + k0, DM, tid, As);
        load_tileB_t(W + (size_t)n0 * DM + k0, DM, tid, Ws);
        __syncthreads();
        mm_inner32(As, Ws, ty, tx, acc);
        __syncthreads();
    }
    #pragma unroll
    for (int pr = 0; pr < 4; pr++) {
        float4 lo, hi;
        unpack2(acc[pr][0], lo.x, hi.x);
        unpack2(acc[pr][1], lo.y, hi.y);
        unpack2(acc[pr][2], lo.z, hi.z);
        unpack2(acc[pr][3], lo.w, hi.w);
        size_t r = (size_t)(m0 + ty * 8 + pr * 2) * DM + n0 + tx * 4;
        *(float4*)&C[r] = lo;
        *(float4*)&C[r + DM] = hi;
    }
}

// ---------------- scores: attn = 0.125 * Q @ K^T per (b,h) ----------------
__global__ __launch_bounds__(256) void scores_kernel(const float* __restrict__ qp,
                                                     const float* __restrict__ kp,
                                                     float* __restrict__ attn) {
    __shared__ float As[32][AT_PITCH];
    __shared__ float Ws[32][BT_PITCH];
    int tid = threadIdx.x;
    int tx = tid & 15, ty = tid >> 4;
    int bh = blockIdx.z;
    int b = bh >> 3, h = bh & 7;
    int sq0 = blockIdx.y * 128, sk0 = blockIdx.x * 64;
    ull acc[4][4] = {};
    #pragma unroll
    for (int dc = 0; dc < 64; dc += 32) {
        load_tileA_t(qp + ((size_t)b * S_ + sq0) * DM + h * 64 + dc, DM, tid, As);
        load_tileB_t(kp + ((size_t)b * S_ + sk0) * DM + h * 64 + dc, DM, tid, Ws);
        __syncthreads();
        mm_inner32(As, Ws, ty, tx, acc);
        __syncthreads();
    }
    #pragma unroll
    for (int pr = 0; pr < 4; pr++) {
        float4 lo, hi;
        unpack2(acc[pr][0], lo.x, hi.x);
        unpack2(acc[pr][1], lo.y, hi.y);
        unpack2(acc[pr][2], lo.z, hi.z);
        unpack2(acc[pr][3], lo.w, hi.w);
        lo.x *= 0.125f; lo.y *= 0.125f; lo.z *= 0.125f; lo.w *= 0.125f;
        hi.x *= 0.125f; hi.y *= 0.125f; hi.z *= 0.125f; hi.w *= 0.125f;
        size_t r = ((size_t)bh * S_ + sq0 + ty * 8 + pr * 2) * S_ + sk0 + tx * 4;
        *(float4*)&attn[r] = lo;
        *(float4*)&attn[r + S_] = hi;
    }
}

// ---------------- softmax in place over rows of 2048 (float4) ----------------
__global__ __launch_bounds__(256) void softmax_kernel(float* __restrict__ attn) {
    size_t row = blockIdx.x;
    float4* p = (float4*)(attn + row * (size_t)S_);
    int tid = threadIdx.x;
    float4 v0 = p[tid], v1 = p[tid + 256];
    float m = fmaxf(fmaxf(fmaxf(v0.x, v0.y), fmaxf(v0.z, v0.w)),
                    fmaxf(fmaxf(v1.x, v1.y), fmaxf(v1.z, v1.w)));
    __shared__ float red[256];
    red[tid] = m;
    __syncthreads();
    for (int o = 128; o > 0; o >>= 1) { if (tid < o) red[tid] = fmaxf(red[tid], red[tid + o]); __syncthreads(); }
    m = red[0];
    __syncthreads();
    v0.x = __expf(v0.x - m); v0.y = __expf(v0.y - m); v0.z = __expf(v0.z - m); v0.w = __expf(v0.w - m);
    v1.x = __expf(v1.x - m); v1.y = __expf(v1.y - m); v1.z = __expf(v1.z - m); v1.w = __expf(v1.w - m);
    float s = v0.x + v0.y + v0.z + v0.w + v1.x + v1.y + v1.z + v1.w;
    red[tid] = s;
    __syncthreads();
    for (int o = 128; o > 0; o >>= 1) { if (tid < o) red[tid] += red[tid + o]; __syncthreads(); }
    float inv = 1.0f / red[0];
    v0.x *= inv; v0.y *= inv; v0.z *= inv; v0.w *= inv;
    v1.x *= inv; v1.y *= inv; v1.z *= inv; v1.w *= inv;
    p[tid] = v0;
    p[tid + 256] = v1;
}

// ---------------- oh = attn @ V per (b,h) ----------------
__global__ __launch_bounds__(256) void av_kernel(const float* __restrict__ attn,
                                                 const float* __restrict__ vp,
                                                 float* __restrict__ oh) {
    __shared__ float Ps[32][AT_PITCH];   // transposed attn chunk [sk][sq]
    __shared__ float Vs[32][BT_PITCH];   // natural V chunk [sk][dv]
    int tid = threadIdx.x;
    int tx = tid & 15, ty = tid >> 4;
    int bh = blockIdx.y;
    int b = bh >> 3, h = bh & 7;
    int sq0 = blockIdx.x * 128;
    ull acc[4][4] = {};
    for (int sk0 = 0; sk0 < S_; sk0 += 32) {
        load_tileA_t(attn + ((size_t)bh * S_ + sq0) * S_ + sk0, S_, tid, Ps);
        #pragma unroll
        for (int i = 0; i < 2; i++) {
            int lin = tid + i * 256;
            int r = lin >> 4, cg = (lin & 15) * 4;
            float4 f = *(const float4*)&vp[((size_t)b * S_ + sk0 + r) * DM + h * 64 + cg];
            *(float4*)&Vs[r][cg] = f;
        }
        __syncthreads();
        mm_inner32(Ps, Vs, ty, tx, acc);
        __syncthreads();
    }
    #pragma unroll
    for (int pr = 0; pr < 4; pr++) {
        float4 lo, hi;
        unpack2(acc[pr][0], lo.x, hi.x);
        unpack2(acc[pr][1], lo.y, hi.y);
        unpack2(acc[pr][2], lo.z, hi.z);
        unpack2(acc[pr][3], lo.w, hi.w);
        size_t r = ((size_t)b * S_ + sq0 + ty * 8 + pr * 2) * DM + h * 64 + tx * 4;
        *(float4*)&oh[r] = lo;
        *(float4*)&oh[r + DM] = hi;
    }
}

extern "C" void kernel_launch(void* const* d_in, const int* in_sizes, int n_in,
                              void* d_out, int out_size) {
    const float* q    = (const float*)d_in[0];
    const float* k    = (const float*)d_in[1];
    const float* v    = (const float*)d_in[2];
    const float* W_Q  = (const float*)d_in[3];
    const float* W_K  = (const float*)d_in[4];
    const float* W_V  = (const float*)d_in[5];
    const float* W_fc = (const float*)d_in[6];
    const float* ln_g = (const float*)d_in[7];
    const float* ln_b = (const float*)d_in[8];

    float* out  = (float*)d_out;                       // [B,S,512]
    float* attn = out + (size_t)B_ * S_ * DM;          // [B,H,S,S]

    float *buf, *qp, *kp, *vp, *oh;
    cudaGetSymbolAddress((void**)&buf, g_buf);
    cudaGetSymbolAddress((void**)&qp,  g_qp);
    cudaGetSymbolAddress((void**)&kp,  g_kp);
    cudaGetSymbolAddress((void**)&vp,  g_vp);
    cudaGetSymbolAddress((void**)&oh,  g_oh);

    const int ROWS = B_ * S_;                          // 8192
    dim3 gemm_grid(DM / 64, ROWS / 128);               // (8, 64)

    // Q path
    ln_kernel<<<ROWS, 256>>>(q, buf, ln_g, ln_b);
    proj_gemm<<<gemm_grid, 256>>>(buf, W_Q, qp);
    // K path
    ln_kernel<<<ROWS, 256>>>(k, buf, ln_g, ln_b);
    proj_gemm<<<gemm_grid, 256>>>(buf, W_K, kp);
    // V path
    ln_kernel<<<ROWS, 256>>>(v, buf, ln_g, ln_b);
    proj_gemm<<<gemm_grid, 256>>>(buf, W_V, vp);

    // Attention
    scores_kernel<<<dim3(S_ / 64, S_ / 128, B_ * H_), 256>>>(qp, kp, attn);
    softmax_kernel<<<B_ * H_ * S_, 256>>>(attn);
    av_kernel<<<dim3(S_ / 128, B_ * H_), 256>>>(attn, vp, oh);

    // Output LN + fc
    ln_kernel<<<ROWS, 256>>>(oh, buf, ln_g, ln_b);
    proj_gemm<<<gemm_grid, 256>>>(buf, W_fc, out);
}

// round 7
// speedup vs baseline: 1.3638x; 1.0159x over previous
#include <cuda_runtime.h>
#include <math.h>

#define B_ 4
#define S_ 2048
#define DM 512
#define H_ 8

typedef unsigned long long ull;

__device__ __forceinline__ ull ffma2(ull a, ull b, ull c) {
    ull d;
    asm("fma.rn.f32x2 %0, %1, %2, %3;" : "=l"(d) : "l"(a), "l"(b), "l"(c));
    return d;
}
__device__ __forceinline__ ull pack2(float x, float y) {
    ull r;
    asm("mov.b64 %0, {%1, %2};" : "=l"(r) : "f"(x), "f"(y));
    return r;
}
__device__ __forceinline__ void unpack2(ull v, float& x, float& y) {
    asm("mov.b64 {%0, %1}, %2;" : "=f"(x), "=f"(y) : "l"(v));
}

// Scratch (device globals — no runtime allocation allowed)
__device__ float g_buf[(size_t)B_*S_*DM];
__device__ float g_qp [(size_t)B_*S_*DM];
__device__ float g_kp [(size_t)B_*S_*DM];
__device__ float g_vp [(size_t)B_*S_*DM];
__device__ float g_oh [(size_t)B_*S_*DM];

// ---------------- LayerNorm: one block per row of 512 ----------------
__global__ void ln_kernel(const float* __restrict__ x, float* __restrict__ y,
                          const float* __restrict__ g, const float* __restrict__ bb) {
    int row = blockIdx.x;
    int tid = threadIdx.x;                   // 256 threads
    const float* xr = x + (size_t)row * DM;
    float v0 = xr[tid], v1 = xr[tid + 256];
    __shared__ float red[256];
    red[tid] = v0 + v1;
    __syncthreads();
    for (int o = 128; o > 0; o >>= 1) { if (tid < o) red[tid] += red[tid + o]; __syncthreads(); }
    float mu = red[0] * (1.0f / DM);
    __syncthreads();
    float d0 = v0 - mu, d1 = v1 - mu;
    red[tid] = d0 * d0 + d1 * d1;
    __syncthreads();
    for (int o = 128; o > 0; o >>= 1) { if (tid < o) red[tid] += red[tid + o]; __syncthreads(); }
    float rstd = rsqrtf(red[0] * (1.0f / DM) + 1e-5f);
    float* yr = y + (size_t)row * DM;
    yr[tid]       = d0 * rstd * g[tid]       + bb[tid];
    yr[tid + 256] = d1 * rstd * g[tid + 256] + bb[tid + 256];
}

// =====================================================================
// 8x8 FFMA2 micro-kernel. Per k-step: 2x ulonglong2 (A row pairs) +
// 2x float4 (B cols) + 8 pack + 32 FFMA2.  acc[pr][c] lanes =
// rows (ro+2pr, ro+2pr+1), col co+c.
// =====================================================================

#define AP 132    // pitch for 128-wide transposed tiles (528B rows, 16B-aligned)
#define AP256 260 // pitch for 256-wide (1040B rows, 16B-aligned)
#define VP 68     // pitch for 64-wide V tile

template<int PA, int PB>
__device__ __forceinline__ void mm_chunk16(const float (*As)[PA], const float (*Bs)[PB],
                                           int ro, int co, ull acc[4][8]) {
    #pragma unroll
    for (int kk = 0; kk < 16; kk++) {
        ulonglong2 a0 = *(const ulonglong2*)&As[kk][ro];
        ulonglong2 a1 = *(const ulonglong2*)&As[kk][ro + 4];
        float4 f0 = *(const float4*)&Bs[kk][co];
        float4 f1 = *(const float4*)&Bs[kk][co + 4];
        ull aa[4] = {a0.x, a0.y, a1.x, a1.y};
        ull bb[8] = {pack2(f0.x, f0.x), pack2(f0.y, f0.y),
                     pack2(f0.z, f0.z), pack2(f0.w, f0.w),
                     pack2(f1.x, f1.x), pack2(f1.y, f1.y),
                     pack2(f1.z, f1.z), pack2(f1.w, f1.w)};
        #pragma unroll
        for (int r = 0; r < 4; r++)
            #pragma unroll
            for (int c = 0; c < 8; c++)
                acc[r][c] = ffma2(aa[r], bb[c], acc[r][c]);
    }
}

// Epilogue: store acc (8 rows x 8 cols) at C[row base rb, col cb], row stride ld.
__device__ __forceinline__ void store_acc(float* __restrict__ C, size_t rb_off, size_t ld,
                                          ull acc[4][8], float scale) {
    #pragma unroll
    for (int pr = 0; pr < 4; pr++) {
        float4 lo0, lo1, hi0, hi1;
        unpack2(acc[pr][0], lo0.x, hi0.x);
        unpack2(acc[pr][1], lo0.y, hi0.y);
        unpack2(acc[pr][2], lo0.z, hi0.z);
        unpack2(acc[pr][3], lo0.w, hi0.w);
        unpack2(acc[pr][4], lo1.x, hi1.x);
        unpack2(acc[pr][5], lo1.y, hi1.y);
        unpack2(acc[pr][6], lo1.z, hi1.z);
        unpack2(acc[pr][7], lo1.w, hi1.w);
        lo0.x *= scale; lo0.y *= scale; lo0.z *= scale; lo0.w *= scale;
        lo1.x *= scale; lo1.y *= scale; lo1.z *= scale; lo1.w *= scale;
        hi0.x *= scale; hi0.y *= scale; hi0.z *= scale; hi0.w *= scale;
        hi1.x *= scale; hi1.y *= scale; hi1.z *= scale; hi1.w *= scale;
        size_t r0 = rb_off + (size_t)(pr * 2) * ld;
        *(float4*)&C[r0]          = lo0;
        *(float4*)&C[r0 + 4]      = lo1;
        *(float4*)&C[r0 + ld]     = hi0;
        *(float4*)&C[r0 + ld + 4] = hi1;
    }
}

// ---------------- Projection GEMM: C[M,512] = A[M,512] @ W^T ----------------
// grid (DM/128, M/128), 256 threads, tile 128x128, K-chunks of 16, double-buffered.
__global__ __launch_bounds__(256) void proj_gemm(const float* __restrict__ A,
                                                 const float* __restrict__ W,
                                                 float* __restrict__ C) {
    __shared__ float As[2][16][AP];
    __shared__ float Bs[2][16][AP];
    int tid = threadIdx.x;
    int tx = tid & 15, ty = tid >> 4;
    int m0 = blockIdx.y * 128, n0 = blockIdx.x * 128;
    const float* Ab = A + (size_t)m0 * DM;
    const float* Wb = W + (size_t)n0 * DM;

    float4 sa[2], sb[2];
    #pragma unroll
    for (int i = 0; i < 2; i++) {
        int lin = tid + i * 256, r = lin >> 2, kg = (lin & 3) * 4;
        sa[i] = *(const float4*)&Ab[(size_t)r * DM + kg];
        sb[i] = *(const float4*)&Wb[(size_t)r * DM + kg];
    }
    #pragma unroll
    for (int i = 0; i < 2; i++) {
        int lin = tid + i * 256, r = lin >> 2, kg = (lin & 3) * 4;
        As[0][kg][r] = sa[i].x; As[0][kg+1][r] = sa[i].y; As[0][kg+2][r] = sa[i].z; As[0][kg+3][r] = sa[i].w;
        Bs[0][kg][r] = sb[i].x; Bs[0][kg+1][r] = sb[i].y; Bs[0][kg+2][r] = sb[i].z; Bs[0][kg+3][r] = sb[i].w;
    }
    __syncthreads();

    ull acc[4][8] = {};
    const int NC = DM / 16;   // 32 chunks
    for (int c = 0; c < NC; c++) {
        int cur = c & 1, nxt = cur ^ 1;
        if (c + 1 < NC) {
            int k0 = (c + 1) * 16;
            #pragma unroll
            for (int i = 0; i < 2; i++) {
                int lin = tid + i * 256, r = lin >> 2, kg = (lin & 3) * 4;
                sa[i] = *(const float4*)&Ab[(size_t)r * DM + k0 + kg];
                sb[i] = *(const float4*)&Wb[(size_t)r * DM + k0 + kg];
            }
        }
        mm_chunk16<AP, AP>(As[cur], Bs[cur], ty * 8, tx * 8, acc);
        if (c + 1 < NC) {
            #pragma unroll
            for (int i = 0; i < 2; i++) {
                int lin = tid + i * 256, r = lin >> 2, kg = (lin & 3) * 4;
                As[nxt][kg][r] = sa[i].x; As[nxt][kg+1][r] = sa[i].y; As[nxt][kg+2][r] = sa[i].z; As[nxt][kg+3][r] = sa[i].w;
                Bs[nxt][kg][r] = sb[i].x; Bs[nxt][kg+1][r] = sb[i].y; Bs[nxt][kg+2][r] = sb[i].z; Bs[nxt][kg+3][r] = sb[i].w;
            }
        }
        __syncthreads();
    }
    store_acc(C, (size_t)(m0 + ty * 8) * DM + n0 + tx * 8, DM, acc, 1.0f);
}

// ---------------- scores: attn = 0.125 * Q @ K^T per (b,h) ----------------
// grid (S/128 [sk], S/128 [sq], B*H), tile 128x128, K=64 in 4 chunks.
__global__ __launch_bounds__(256) void scores_kernel(const float* __restrict__ qp,
                                                     const float* __restrict__ kp,
                                                     float* __restrict__ attn) {
    __shared__ float As[2][16][AP];
    __shared__ float Bs[2][16][AP];
    int tid = threadIdx.x;
    int tx = tid & 15, ty = tid >> 4;
    int bh = blockIdx.z;
    int b = bh >> 3, h = bh & 7;
    int sq0 = blockIdx.y * 128, sk0 = blockIdx.x * 128;
    const float* Qb = qp + ((size_t)b * S_ + sq0) * DM + h * 64;
    const float* Kb = kp + ((size_t)b * S_ + sk0) * DM + h * 64;

    float4 sa[2], sb[2];
    #pragma unroll
    for (int i = 0; i < 2; i++) {
        int lin = tid + i * 256, r = lin >> 2, kg = (lin & 3) * 4;
        sa[i] = *(const float4*)&Qb[(size_t)r * DM + kg];
        sb[i] = *(const float4*)&Kb[(size_t)r * DM + kg];
    }
    #pragma unroll
    for (int i = 0; i < 2; i++) {
        int lin = tid + i * 256, r = lin >> 2, kg = (lin & 3) * 4;
        As[0][kg][r] = sa[i].x; As[0][kg+1][r] = sa[i].y; As[0][kg+2][r] = sa[i].z; As[0][kg+3][r] = sa[i].w;
        Bs[0][kg][r] = sb[i].x; Bs[0][kg+1][r] = sb[i].y; Bs[0][kg+2][r] = sb[i].z; Bs[0][kg+3][r] = sb[i].w;
    }
    __syncthreads();

    ull acc[4][8] = {};
    const int NC = 4;   // K=64
    for (int c = 0; c < NC; c++) {
        int cur = c & 1, nxt = cur ^ 1;
        if (c + 1 < NC) {
            int k0 = (c + 1) * 16;
            #pragma unroll
            for (int i = 0; i < 2; i++) {
                int lin = tid + i * 256, r = lin >> 2, kg = (lin & 3) * 4;
                sa[i] = *(const float4*)&Qb[(size_t)r * DM + k0 + kg];
                sb[i] = *(const float4*)&Kb[(size_t)r * DM + k0 + kg];
            }
        }
        mm_chunk16<AP, AP>(As[cur], Bs[cur], ty * 8, tx * 8, acc);
        if (c + 1 < NC) {
            #pragma unroll
            for (int i = 0; i < 2; i++) {
                int lin = tid + i * 256, r = lin >> 2, kg = (lin & 3) * 4;
                As[nxt][kg][r] = sa[i].x; As[nxt][kg+1][r] = sa[i].y; As[nxt][kg+2][r] = sa[i].z; As[nxt][kg+3][r] = sa[i].w;
                Bs[nxt][kg][r] = sb[i].x; Bs[nxt][kg+1][r] = sb[i].y; Bs[nxt][kg+2][r] = sb[i].z; Bs[nxt][kg+3][r] = sb[i].w;
            }
        }
        __syncthreads();
    }
    store_acc(attn, ((size_t)bh * S_ + sq0 + ty * 8) * S_ + sk0 + tx * 8, S_, acc, 0.125f);
}

// ---------------- softmax in place over rows of 2048 (float4) ----------------
__global__ __launch_bounds__(256) void softmax_kernel(float* __restrict__ attn) {
    size_t row = blockIdx.x;
    float4* p = (float4*)(attn + row * (size_t)S_);
    int tid = threadIdx.x;
    float4 v0 = p[tid], v1 = p[tid + 256];
    float m = fmaxf(fmaxf(fmaxf(v0.x, v0.y), fmaxf(v0.z, v0.w)),
                    fmaxf(fmaxf(v1.x, v1.y), fmaxf(v1.z, v1.w)));
    __shared__ float red[256];
    red[tid] = m;
    __syncthreads();
    for (int o = 128; o > 0; o >>= 1) { if (tid < o) red[tid] = fmaxf(red[tid], red[tid + o]); __syncthreads(); }
    m = red[0];
    __syncthreads();
    v0.x = __expf(v0.x - m); v0.y = __expf(v0.y - m); v0.z = __expf(v0.z - m); v0.w = __expf(v0.w - m);
    v1.x = __expf(v1.x - m); v1.y = __expf(v1.y - m); v1.z = __expf(v1.z - m); v1.w = __expf(v1.w - m);
    float s = v0.x + v0.y + v0.z + v0.w + v1.x + v1.y + v1.z + v1.w;
    red[tid] = s;
    __syncthreads();
    for (int o = 128; o > 0; o >>= 1) { if (tid < o) red[tid] += red[tid + o]; __syncthreads(); }
    float inv = 1.0f / red[0];
    v0.x *= inv; v0.y *= inv; v0.z *= inv; v0.w *= inv;
    v1.x *= inv; v1.y *= inv; v1.z *= inv; v1.w *= inv;
    p[tid] = v0;
    p[tid + 256] = v1;
}

// ---------------- oh = attn @ V per (b,h) ----------------
// grid (S/256 [sq], B*H), tile 256x64, 256 threads (32x8), 8x8 per thread,
// sk chunks of 16, double-buffered.
__global__ __launch_bounds__(256) void av_kernel(const float* __restrict__ attn,
                                                 const float* __restrict__ vp,
                                                 float* __restrict__ oh) {
    __shared__ float Ps[2][16][AP256];   // transposed attn chunk [sk][sq]
    __shared__ float Vs[2][16][VP];      // natural V chunk [sk][dv]
    int tid = threadIdx.x;
    int tx = tid & 7, ty = tid >> 3;     // 8 col groups, 32 row groups
    int bh = blockIdx.y;
    int b = bh >> 3, h = bh & 7;
    int sq0 = blockIdx.x * 256;
    const float* Pb = attn + ((size_t)bh * S_ + sq0) * S_;
    const float* Vb = vp + (size_t)b * S_ * DM + h * 64;

    float4 sp[4], sv;
    {
        #pragma unroll
        for (int i = 0; i < 4; i++) {
            int lin = tid + i * 256, r = lin >> 2, kg = (lin & 3) * 4;
            sp[i] = *(const float4*)&Pb[(size_t)r * S_ + kg];
        }
        int vr = tid >> 4, vc = (tid & 15) * 4;
        sv = *(const float4*)&Vb[(size_t)vr * DM + vc];
        #pragma unroll
        for (int i = 0; i < 4; i++) {
            int lin = tid + i * 256, r = lin >> 2, kg = (lin & 3) * 4;
            Ps[0][kg][r] = sp[i].x; Ps[0][kg+1][r] = sp[i].y; Ps[0][kg+2][r] = sp[i].z; Ps[0][kg+3][r] = sp[i].w;
        }
        *(float4*)&Vs[0][vr][vc] = sv;
    }
    __syncthreads();

    ull acc[4][8] = {};
    const int NC = S_ / 16;   // 128 chunks
    for (int c = 0; c < NC; c++) {
        int cur = c & 1, nxt = cur ^ 1;
        int vr = tid >> 4, vc = (tid & 15) * 4;
        if (c + 1 < NC) {
            int k0 = (c + 1) * 16;
            #pragma unroll
            for (int i = 0; i < 4; i++) {
                int lin = tid + i * 256, r = lin >> 2, kg = (lin & 3) * 4;
                sp[i] = *(const float4*)&Pb[(size_t)r * S_ + k0 + kg];
            }
            sv = *(const float4*)&Vb[(size_t)(k0 + vr) * DM + vc];
        }
        mm_chunk16<AP256, VP>(Ps[cur], Vs[cur], ty * 8, tx * 8, acc);
        if (c + 1 < NC) {
            #pragma unroll
            for (int i = 0; i < 4; i++) {
                int lin = tid + i * 256, r = lin >> 2, kg = (lin & 3) * 4;
                Ps[nxt][kg][r] = sp[i].x; Ps[nxt][kg+1][r] = sp[i].y; Ps[nxt][kg+2][r] = sp[i].z; Ps[nxt][kg+3][r] = sp[i].w;
            }
            *(float4*)&Vs[nxt][vr][vc] = sv;
        }
        __syncthreads();
    }
    store_acc(oh, ((size_t)b * S_ + sq0 + ty * 8) * DM + h * 64 + tx * 8, DM, acc, 1.0f);
}

extern "C" void kernel_launch(void* const* d_in, const int* in_sizes, int n_in,
                              void* d_out, int out_size) {
    const float* q    = (const float*)d_in[0];
    const float* k    = (const float*)d_in[1];
    const float* v    = (const float*)d_in[2];
    const float* W_Q  = (const float*)d_in[3];
    const float* W_K  = (const float*)d_in[4];
    const float* W_V  = (const float*)d_in[5];
    const float* W_fc = (const float*)d_in[6];
    const float* ln_g = (const float*)d_in[7];
    const float* ln_b = (const float*)d_in[8];

    float* out  = (float*)d_out;                       // [B,S,512]
    float* attn = out + (size_t)B_ * S_ * DM;          // [B,H,S,S]

    float *buf, *qp, *kp, *vp, *oh;
    cudaGetSymbolAddress((void**)&buf, g_buf);
    cudaGetSymbolAddress((void**)&qp,  g_qp);
    cudaGetSymbolAddress((void**)&kp,  g_kp);
    cudaGetSymbolAddress((void**)&vp,  g_vp);
    cudaGetSymbolAddress((void**)&oh,  g_oh);

    const int ROWS = B_ * S_;                          // 8192
    dim3 gemm_grid(DM / 128, ROWS / 128);              // (4, 64)

    // Q path
    ln_kernel<<<ROWS, 256>>>(q, buf, ln_g, ln_b);
    proj_gemm<<<gemm_grid, 256>>>(buf, W_Q, qp);
    // K path
    ln_kernel<<<ROWS, 256>>>(k, buf, ln_g, ln_b);
    proj_gemm<<<gemm_grid, 256>>>(buf, W_K, kp);
    // V path
    ln_kernel<<<ROWS, 256>>>(v, buf, ln_g, ln_b);
    proj_gemm<<<gemm_grid, 256>>>(buf, W_V, vp);

    // Attention
    scores_kernel<<<dim3(S_ / 128, S_ / 128, B_ * H_), 256>>>(qp, kp, attn);
    softmax_kernel<<<B_ * H_ * S_, 256>>>(attn);
    av_kernel<<<dim3(S_ / 256, B_ * H_), 256>>>(attn, vp, oh);

    // Output LN + fc
    ln_kernel<<<ROWS, 256>>>(oh, buf, ln_g, ln_b);
    proj_gemm<<<gemm_grid, 256>>>(buf, W_fc, out);
}